// round 3
// baseline (speedup 1.0000x reference)
#include <cuda_runtime.h>

#define NB_VARS 2000000
#define M0 4000000
#define M1 1000000
#define M2 500000
#define M3 125000
#define E1 8000000
#define E3 1000000

// Scratch (allocation-free rule: __device__ globals)
__device__ float g_y0[M0];
__device__ float g_y1[M1];
__device__ float g_y2[M2];

// Fused input encoding: x = [0, 1, p0, 1-p0, p1, 1-p1, ...]
__device__ __forceinline__ float leaf_val(const float* __restrict__ xp, int idx) {
    if (idx >= 2) {
        float p = __ldg(xp + ((idx - 2) >> 1));
        return (idx & 1) ? (1.0f - p) : p;
    }
    return (float)idx;  // 0 -> 0.0, 1 -> 1.0
}

// Layer 0: 8 products per thread (16 gathers in flight), 2x float4 store.
// Also zeroes g_y1 and d_out (stream order guarantees completion before segsum kernels).
__global__ void __launch_bounds__(256) layer0_kernel(const float* __restrict__ xp,
                                                     const int4* __restrict__ ix,
                                                     float* __restrict__ out_zero) {
    int t = blockIdx.x * blockDim.x + threadIdx.x;     // [0, M0/8)
    if (t < M1 / 4) ((float4*)g_y1)[t] = make_float4(0.f, 0.f, 0.f, 0.f);
    if (t < M3 / 4) ((float4*)out_zero)[t] = make_float4(0.f, 0.f, 0.f, 0.f);
    if (t >= M0 / 8) return;
    int4 a = __ldg(ix + 4 * t);
    int4 b = __ldg(ix + 4 * t + 1);
    int4 c = __ldg(ix + 4 * t + 2);
    int4 d = __ldg(ix + 4 * t + 3);
    float4 r0, r1;
    r0.x = leaf_val(xp, a.x) * leaf_val(xp, a.y);
    r0.y = leaf_val(xp, a.z) * leaf_val(xp, a.w);
    r0.z = leaf_val(xp, b.x) * leaf_val(xp, b.y);
    r0.w = leaf_val(xp, b.z) * leaf_val(xp, b.w);
    r1.x = leaf_val(xp, c.x) * leaf_val(xp, c.y);
    r1.y = leaf_val(xp, c.z) * leaf_val(xp, c.w);
    r1.z = leaf_val(xp, d.x) * leaf_val(xp, d.y);
    r1.w = leaf_val(xp, d.z) * leaf_val(xp, d.w);
    ((float4*)g_y0)[2 * t + 0] = r0;
    ((float4*)g_y0)[2 * t + 1] = r1;
}

// Layer 2: 8 products per thread over g_y1 -> g_y2.
__global__ void __launch_bounds__(256) layer2_kernel(const int4* __restrict__ ix) {
    int t = blockIdx.x * blockDim.x + threadIdx.x;     // [0, M2/8)
    if (t >= M2 / 8) return;
    int4 a = __ldg(ix + 4 * t);
    int4 b = __ldg(ix + 4 * t + 1);
    int4 c = __ldg(ix + 4 * t + 2);
    int4 d = __ldg(ix + 4 * t + 3);
    float4 r0, r1;
    r0.x = g_y1[a.x] * g_y1[a.y];
    r0.y = g_y1[a.z] * g_y1[a.w];
    r0.z = g_y1[b.x] * g_y1[b.y];
    r0.w = g_y1[b.z] * g_y1[b.w];
    r1.x = g_y1[c.x] * g_y1[c.y];
    r1.y = g_y1[c.z] * g_y1[c.w];
    r1.z = g_y1[d.x] * g_y1[d.y];
    r1.w = g_y1[d.z] * g_y1[d.w];
    ((float4*)g_y2)[2 * t + 0] = r0;
    ((float4*)g_y2)[2 * t + 1] = r1;
}

// Sorted segment-sum, 8 edges/thread, scan-free:
// local run-merge + one atomicAdd (-> REDG) per local run. Runs spanning thread
// boundaries contribute via multiple atomics — still correct.
__device__ __forceinline__ void segsum8(const int4* __restrict__ ix_in,
                                        const int4* __restrict__ ix_out,
                                        const float* __restrict__ src,
                                        float* __restrict__ dst, int nthreads) {
    int t = blockIdx.x * blockDim.x + threadIdx.x;
    if (t >= nthreads) return;

    int4 s0 = __ldg(ix_out + 2 * t);
    int4 s1 = __ldg(ix_out + 2 * t + 1);
    int4 g0 = __ldg(ix_in + 2 * t);
    int4 g1 = __ldg(ix_in + 2 * t + 1);

    // 8 independent gathers (full MLP before any dependent work)
    float v0 = __ldg(src + g0.x);
    float v1 = __ldg(src + g0.y);
    float v2 = __ldg(src + g0.z);
    float v3 = __ldg(src + g0.w);
    float v4 = __ldg(src + g1.x);
    float v5 = __ldg(src + g1.y);
    float v6 = __ldg(src + g1.z);
    float v7 = __ldg(src + g1.w);

    int  segs[8] = {s0.x, s0.y, s0.z, s0.w, s1.x, s1.y, s1.z, s1.w};
    float vals[8] = {v0, v1, v2, v3, v4, v5, v6, v7};

    int cur = segs[0];
    float acc = vals[0];
    #pragma unroll
    for (int i = 1; i < 8; i++) {
        if (segs[i] == cur) {
            acc += vals[i];
        } else {
            atomicAdd(dst + cur, acc);
            cur = segs[i];
            acc = vals[i];
        }
    }
    atomicAdd(dst + cur, acc);
}

__global__ void __launch_bounds__(256) segsum1_kernel(const int4* __restrict__ ix_in,
                                                      const int4* __restrict__ ix_out) {
    segsum8(ix_in, ix_out, g_y0, g_y1, E1 / 8);
}

__global__ void __launch_bounds__(256) segsum3_kernel(const int4* __restrict__ ix_in,
                                                      const int4* __restrict__ ix_out,
                                                      float* __restrict__ out) {
    segsum8(ix_in, ix_out, g_y2, out, E3 / 8);
}

extern "C" void kernel_launch(void* const* d_in, const int* in_sizes, int n_in,
                              void* d_out, int out_size) {
    const float* x_pos   = (const float*)d_in[0];
    const int*   ix_in0  = (const int*)d_in[1];
    const int*   ix_in1  = (const int*)d_in[2];
    const int*   ix_out1 = (const int*)d_in[3];
    const int*   ix_in2  = (const int*)d_in[4];
    const int*   ix_in3  = (const int*)d_in[5];
    const int*   ix_out3 = (const int*)d_in[6];
    float* out = (float*)d_out;

    const int B = 256;
    layer0_kernel <<<(M0 / 8 + B - 1) / B, B>>>(x_pos, (const int4*)ix_in0, out);
    segsum1_kernel<<<(E1 / 8 + B - 1) / B, B>>>((const int4*)ix_in1, (const int4*)ix_out1);
    layer2_kernel <<<(M2 / 8 + B - 1) / B, B>>>((const int4*)ix_in2);
    segsum3_kernel<<<(E3 / 8 + B - 1) / B, B>>>((const int4*)ix_in3, (const int4*)ix_out3, out);
}

// round 4
// speedup vs baseline: 1.0970x; 1.0970x over previous
#include <cuda_runtime.h>

#define NB_VARS 2000000
#define M0 4000000
#define M1 1000000
#define M2 500000
#define M3 125000
#define E1 8000000
#define E3 1000000

// Scratch (allocation-free rule: __device__ globals)
__device__ float g_y0[M0];
__device__ float g_y1[M1];
__device__ float g_y2[M2];

// Fused input encoding: x = [0, 1, p0, 1-p0, p1, 1-p1, ...]
__device__ __forceinline__ float leaf_val(const float* __restrict__ xp, int idx) {
    if (idx >= 2) {
        float p = __ldg(xp + ((idx - 2) >> 1));
        return (idx & 1) ? (1.0f - p) : p;
    }
    return (float)idx;  // 0 -> 0.0, 1 -> 1.0
}

// Layer 0: 4 products per thread (8 gathers in flight), float4 store.
// Also zeroes g_y1 and d_out (stream order guarantees completion before segsums).
__global__ void __launch_bounds__(256) layer0_kernel(const float* __restrict__ xp,
                                                     const int4* __restrict__ ix,
                                                     float* __restrict__ out_zero) {
    int t = blockIdx.x * blockDim.x + threadIdx.x;     // [0, M0/4)
    if (t < M1 / 4) ((float4*)g_y1)[t] = make_float4(0.f, 0.f, 0.f, 0.f);
    if (t < M3 / 4) ((float4*)out_zero)[t] = make_float4(0.f, 0.f, 0.f, 0.f);
    if (t >= M0 / 4) return;
    int4 a = __ldg(ix + 2 * t);
    int4 b = __ldg(ix + 2 * t + 1);
    float4 r;
    r.x = leaf_val(xp, a.x) * leaf_val(xp, a.y);
    r.y = leaf_val(xp, a.z) * leaf_val(xp, a.w);
    r.z = leaf_val(xp, b.x) * leaf_val(xp, b.y);
    r.w = leaf_val(xp, b.z) * leaf_val(xp, b.w);
    ((float4*)g_y0)[t] = r;
}

// Layer 2: 4 products per thread over g_y1 -> g_y2.
__global__ void __launch_bounds__(256) layer2_kernel(const int4* __restrict__ ix) {
    int t = blockIdx.x * blockDim.x + threadIdx.x;     // [0, M2/4)
    if (t >= M2 / 4) return;
    int4 a = __ldg(ix + 2 * t);
    int4 b = __ldg(ix + 2 * t + 1);
    float4 r;
    r.x = g_y1[a.x] * g_y1[a.y];
    r.y = g_y1[a.z] * g_y1[a.w];
    r.z = g_y1[b.x] * g_y1[b.y];
    r.w = g_y1[b.z] * g_y1[b.w];
    ((float4*)g_y2)[t] = r;
}

// Sorted segment-sum, 4 edges/thread, scan-free:
// local run-merge + one atomicAdd (compiles to REDG, no return) per local run.
// Runs spanning thread boundaries contribute via multiple atomics — still correct.
__device__ __forceinline__ void segsum4(const int4* __restrict__ ix_in,
                                        const int4* __restrict__ ix_out,
                                        const float* __restrict__ src,
                                        float* __restrict__ dst, int nthreads) {
    int t = blockIdx.x * blockDim.x + threadIdx.x;
    if (t >= nthreads) return;

    int4 s = __ldg(ix_out + t);
    int4 g = __ldg(ix_in + t);

    // 4 independent gathers in flight
    float v0 = __ldg(src + g.x);
    float v1 = __ldg(src + g.y);
    float v2 = __ldg(src + g.z);
    float v3 = __ldg(src + g.w);

    // Local run-merge over the 4 sorted segment ids.
    float acc = v0;
    int cur = s.x;
    if (s.y == cur) acc += v1; else { atomicAdd(dst + cur, acc); cur = s.y; acc = v1; }
    if (s.z == cur) acc += v2; else { atomicAdd(dst + cur, acc); cur = s.z; acc = v2; }
    if (s.w == cur) acc += v3; else { atomicAdd(dst + cur, acc); cur = s.w; acc = v3; }
    atomicAdd(dst + cur, acc);
}

__global__ void __launch_bounds__(256) segsum1_kernel(const int4* __restrict__ ix_in,
                                                      const int4* __restrict__ ix_out) {
    segsum4(ix_in, ix_out, g_y0, g_y1, E1 / 4);
}

__global__ void __launch_bounds__(256) segsum3_kernel(const int4* __restrict__ ix_in,
                                                      const int4* __restrict__ ix_out,
                                                      float* __restrict__ out) {
    segsum4(ix_in, ix_out, g_y2, out, E3 / 4);
}

extern "C" void kernel_launch(void* const* d_in, const int* in_sizes, int n_in,
                              void* d_out, int out_size) {
    const float* x_pos   = (const float*)d_in[0];
    const int*   ix_in0  = (const int*)d_in[1];
    const int*   ix_in1  = (const int*)d_in[2];
    const int*   ix_out1 = (const int*)d_in[3];
    const int*   ix_in2  = (const int*)d_in[4];
    const int*   ix_in3  = (const int*)d_in[5];
    const int*   ix_out3 = (const int*)d_in[6];
    float* out = (float*)d_out;

    const int B = 256;
    layer0_kernel <<<(M0 / 4 + B - 1) / B, B>>>(x_pos, (const int4*)ix_in0, out);
    segsum1_kernel<<<(E1 / 4 + B - 1) / B, B>>>((const int4*)ix_in1, (const int4*)ix_out1);
    layer2_kernel <<<(M2 / 4 + B - 1) / B, B>>>((const int4*)ix_in2);
    segsum3_kernel<<<(E3 / 4 + B - 1) / B, B>>>((const int4*)ix_in3, (const int4*)ix_out3, out);
}